// round 9
// baseline (speedup 1.0000x reference)
#include <cuda_runtime.h>
#include <cstdint>
#include <cstddef>

// Problem dims
#define VOCAB 32000
#define EMB   512
#define HID   512
#define BATCH 64
#define S_LEN 512

// ---------------------------------------------------------------------------
// Scratch (no allocation allowed -> __device__ global)
// ---------------------------------------------------------------------------
__device__ float g_xproj[(size_t)BATCH * S_LEN * HID]; // 64 MB scratch

// ---------------------------------------------------------------------------
// Packed f32x2 helpers (Blackwell)
// ---------------------------------------------------------------------------
__device__ __forceinline__ unsigned long long packdup(float v) {
    unsigned long long r;
    asm("mov.b64 %0, {%1, %1};" : "=l"(r) : "f"(v));
    return r;
}
__device__ __forceinline__ void ffma2(unsigned long long& acc,
                                      unsigned long long a,
                                      unsigned long long b) {
    asm("fma.rn.f32x2 %0, %1, %2, %0;" : "+l"(acc) : "l"(a), "l"(b));
}
__device__ __forceinline__ float2 unpack2(unsigned long long v) {
    float2 f;
    asm("mov.b64 {%0, %1}, %2;" : "=f"(f.x), "=f"(f.y) : "l"(v));
    return f;
}

// ---------------------------------------------------------------------------
// Kernel 1: x_proj = gather(emb, tok) @ W_ih^T + (b_ih + b_hh)
// BM=BN=128, BK=16, 256 threads, 8x8/thread, f32x2 FFMA, conflict-free maps.
// ---------------------------------------------------------------------------
__global__ void __launch_bounds__(256, 2)
xproj_kernel(const void* __restrict__ tok_raw,
             const float* __restrict__ emb,
             const float* __restrict__ W_ih,
             const float* __restrict__ b_ih,
             const float* __restrict__ b_hh)
{
    __shared__ float              As[16][128];      // A tile, [k][m]
    __shared__ unsigned long long Bsd[16][128];     // B tile, [k][n], dup {v,v}
    __shared__ int                toks[128];
    __shared__ int                s_tok64;

    const int tid = threadIdx.x;
    const int m0  = blockIdx.y * 128;
    const int n0  = blockIdx.x * 128;

    // int64 tokens (LE) => odd 32-bit words of the first 32 elements all zero.
    if (tid < 32) {
        int wv = ((const int*)tok_raw)[2 * tid + 1];
        unsigned nz = __ballot_sync(0xffffffffu, wv != 0);
        if (tid == 0) s_tok64 = (nz == 0u);
    }
    __syncthreads();

    if (tid < 128) {
        int m = m0 + tid;
        toks[tid] = s_tok64 ? (int)((const long long*)tok_raw)[m]
                            : ((const int*)tok_raw)[m];
    }
    __syncthreads();

    // Loaders: thread t loads row (t&127), k-seg ((t>>7)*8 .. +8)
    const int ldr_m   = tid & 127;
    const int ldr_seg = (tid >> 7) * 8;
    const float* arow_base = emb  + (size_t)toks[ldr_m] * EMB + ldr_seg;
    const float* brow_base = W_ih + (size_t)(n0 + ldr_m) * EMB + ldr_seg;

    const int ty = tid & 15;   // m sub-tile
    const int tx = tid >> 4;   // n sub-tile

    unsigned long long acc[32]; // acc[i2*8+j]: (m=ty*8+2*i2, m+1) x (n=n0+tx*8+j)
#pragma unroll
    for (int i = 0; i < 32; i++) acc[i] = 0ull;

    for (int kt = 0; kt < EMB / 16; kt++) {
        const int k0 = kt * 16;
        float4 av0 = *(const float4*)(arow_base + k0);
        float4 av1 = *(const float4*)(arow_base + k0 + 4);
        float4 bv0 = *(const float4*)(brow_base + k0);
        float4 bv1 = *(const float4*)(brow_base + k0 + 4);

        __syncthreads();   // previous tile fully consumed
        As[ldr_seg + 0][ldr_m] = av0.x;
        As[ldr_seg + 1][ldr_m] = av0.y;
        As[ldr_seg + 2][ldr_m] = av0.z;
        As[ldr_seg + 3][ldr_m] = av0.w;
        As[ldr_seg + 4][ldr_m] = av1.x;
        As[ldr_seg + 5][ldr_m] = av1.y;
        As[ldr_seg + 6][ldr_m] = av1.z;
        As[ldr_seg + 7][ldr_m] = av1.w;
        Bsd[ldr_seg + 0][ldr_m] = packdup(bv0.x);
        Bsd[ldr_seg + 1][ldr_m] = packdup(bv0.y);
        Bsd[ldr_seg + 2][ldr_m] = packdup(bv0.z);
        Bsd[ldr_seg + 3][ldr_m] = packdup(bv0.w);
        Bsd[ldr_seg + 4][ldr_m] = packdup(bv1.x);
        Bsd[ldr_seg + 5][ldr_m] = packdup(bv1.y);
        Bsd[ldr_seg + 6][ldr_m] = packdup(bv1.z);
        Bsd[ldr_seg + 7][ldr_m] = packdup(bv1.w);
        __syncthreads();

#pragma unroll
        for (int kk = 0; kk < 16; kk++) {
            ulonglong2 a01 = *(const ulonglong2*)&As[kk][ty * 8];
            ulonglong2 a23 = *(const ulonglong2*)&As[kk][ty * 8 + 4];
            unsigned long long ap[4] = { a01.x, a01.y, a23.x, a23.y };
            ulonglong2 b01 = *(const ulonglong2*)&Bsd[kk][tx * 8];
            ulonglong2 b23 = *(const ulonglong2*)&Bsd[kk][tx * 8 + 2];
            ulonglong2 b45 = *(const ulonglong2*)&Bsd[kk][tx * 8 + 4];
            ulonglong2 b67 = *(const ulonglong2*)&Bsd[kk][tx * 8 + 6];
            unsigned long long bd[8] = { b01.x, b01.y, b23.x, b23.y,
                                         b45.x, b45.y, b67.x, b67.y };
#pragma unroll
            for (int i2 = 0; i2 < 4; i2++)
#pragma unroll
                for (int j = 0; j < 8; j++)
                    ffma2(acc[i2 * 8 + j], ap[i2], bd[j]);
        }
    }

    // Epilogue: add (b_ih + b_hh), store
    float bias[8];
    {
        float4 x0 = *(const float4*)(b_ih + n0 + tx * 8);
        float4 x1 = *(const float4*)(b_ih + n0 + tx * 8 + 4);
        float4 y0 = *(const float4*)(b_hh + n0 + tx * 8);
        float4 y1 = *(const float4*)(b_hh + n0 + tx * 8 + 4);
        bias[0] = x0.x + y0.x;  bias[1] = x0.y + y0.y;
        bias[2] = x0.z + y0.z;  bias[3] = x0.w + y0.w;
        bias[4] = x1.x + y1.x;  bias[5] = x1.y + y1.y;
        bias[6] = x1.z + y1.z;  bias[7] = x1.w + y1.w;
    }
#pragma unroll
    for (int i2 = 0; i2 < 4; i2++) {
        float r0[8], r1[8];
#pragma unroll
        for (int j = 0; j < 8; j++) {
            float2 f = unpack2(acc[i2 * 8 + j]);
            r0[j] = f.x + bias[j];
            r1[j] = f.y + bias[j];
        }
        size_t mg = (size_t)(m0 + ty * 8 + i2 * 2);
        float* o0 = g_xproj + mg * HID + n0 + tx * 8;
        float* o1 = o0 + HID;
        *(float4*)(o0)     = make_float4(r0[0], r0[1], r0[2], r0[3]);
        *(float4*)(o0 + 4) = make_float4(r0[4], r0[5], r0[6], r0[7]);
        *(float4*)(o1)     = make_float4(r1[0], r1[1], r1[2], r1[3]);
        *(float4*)(o1 + 4) = make_float4(r1[4], r1[5], r1[6], r1[7]);
    }
}

// ---------------------------------------------------------------------------
// Kernel 2: recurrence, TWO-PHASE SOFTWARE PIPELINED.
// 16 clusters x 8 CTAs x 512 threads; cluster owns 4 batches split into two
// groups of 2 (group 0: batches {0,1}, group 1: {2,3}). Iteration i
// (i = 2t+g, 1024 total): compute+send partials for group g at time t, then
// wait+reduce the PREVIOUS iteration's group — so each group's DSMEM flight
// + mbar wake is hidden behind the other group's compute.
// 4 mbars ([group][slot=t&1]); STEP_TX=4096 (16 x 256B slabs/owner/use).
// ---------------------------------------------------------------------------
#define CSZ 8
#define BG  4
#define KC  64
#define STEP_TX 4096

__global__ void __cluster_dims__(CSZ, 1, 1) __launch_bounds__(512, 1)
rnn_kernel(const float* __restrict__ W_hh, float* __restrict__ out)
{
    __shared__ float h_own[2][2][KC];           // [group][batch-in-group][row] 1 KB
    __shared__ float recv[2][2][CSZ][2 * KC];   // [group][slot][src][rhl*2+b] 16 KB
    __shared__ float stage[4][16][64];          // [i&3][warp][lane*2+b] 16 KB
    __shared__ unsigned long long mbar[4];      // [group*2 + slot]

    const int tid  = threadIdx.x;
    const int w    = tid >> 5;
    const int lane = tid & 31;
    unsigned int rank;
    asm("mov.u32 %0, %%cluster_ctarank;" : "=r"(rank));
    const int batch_base = (blockIdx.x / CSZ) * BG;

    // Register-resident W_hh chunk: thread t holds W_hh[t][rank*64 .. +63]
    unsigned long long Wp[KC / 2];
    {
        const unsigned long long* wrow =
            (const unsigned long long*)(W_hh + (size_t)tid * HID + rank * KC);
#pragma unroll
        for (int i = 0; i < KC / 2; i++) Wp[i] = wrow[i];
    }

    if (tid < 256) ((float*)h_own)[tid] = 0.0f;   // h0 = 0, both groups

    // mbarriers: init + pre-arm all 4 (first uses are iterations 0..3)
    unsigned int mb_sa[4];
#pragma unroll
    for (int m = 0; m < 4; m++)
        mb_sa[m] = (unsigned int)__cvta_generic_to_shared(&mbar[m]);
    if (tid == 0) {
#pragma unroll
        for (int m = 0; m < 4; m++) {
            asm volatile("mbarrier.init.shared.b64 [%0], 1;" :: "r"(mb_sa[m]) : "memory");
            asm volatile("mbarrier.arrive.expect_tx.shared.b64 _, [%0], %1;"
                         :: "r"(mb_sa[m]), "r"(STEP_TX) : "memory");
        }
    }

    // Reduce-role (tid < 128): b = tid&1 (batch in group), rhl = tid>>1 (row)
    const int rb  = tid & 1;
    const int rhl = tid >> 1;

    // Writer-role: warp w -> owner CTA dstw = w>>1, half hh = w&1 (256B slab)
    const unsigned int dstw = (unsigned)(w >> 1);
    const unsigned int hh   = (unsigned)(w & 1);

    const unsigned int stage_sa =
        (unsigned int)__cvta_generic_to_shared(&stage[0][0][0]);
    unsigned int dst_ra[2][2], mb_ra[2][2];
#pragma unroll
    for (int g = 0; g < 2; g++)
#pragma unroll
        for (int sl = 0; sl < 2; sl++) {
            unsigned int la =
                (unsigned int)__cvta_generic_to_shared(&recv[g][sl][rank][0]) + hh * 256u;
            asm("mapa.shared::cluster.u32 %0, %1, %2;" : "=r"(dst_ra[g][sl]) : "r"(la), "r"(dstw));
            asm("mapa.shared::cluster.u32 %0, %1, %2;" : "=r"(mb_ra[g][sl]) : "r"(mb_sa[g * 2 + sl]), "r"(dstw));
        }

    __syncthreads();
    asm volatile("barrier.cluster.arrive.aligned;" ::: "memory");
    asm volatile("barrier.cluster.wait.aligned;"   ::: "memory");

    for (int i = 0; i <= 2 * S_LEN; i++) {
        const int g = i & 1;
        const int t = i >> 1;

        // xp prefetch for THIS iteration's reduce (previous iteration's group)
        float xpv = 0.0f;
        if (i >= 1 && tid < 128) {
            const int gp = (i - 1) & 1, tp = (i - 1) >> 1;
            xpv = __ldg(g_xproj +
                        (size_t)(batch_base + gp * 2 + rb) * S_LEN * HID +
                        (size_t)tp * HID + rank * KC + rhl);
        }

        // ---- compute + send group g at time t ----
        if (i < 2 * S_LEN) {
            float p[2];
#pragma unroll
            for (int b = 0; b < 2; b++) {
                unsigned long long a0 = 0ull, a1 = 0ull;
                const ulonglong2* hb = (const ulonglong2*)h_own[g][b];
#pragma unroll
                for (int k = 0; k < KC / 4; k++) {
                    ulonglong2 hv = hb[k];                 // broadcast LDS.128
                    ffma2(a0, Wp[2 * k],     hv.x);
                    ffma2(a1, Wp[2 * k + 1], hv.y);
                }
                unsigned long long s2;
                asm("add.rn.f32x2 %0, %1, %2;" : "=l"(s2) : "l"(a0), "l"(a1));
                float2 f = unpack2(s2);
                p[b] = f.x + f.y;
            }
            *(float2*)&stage[i & 3][w][lane * 2] = make_float2(p[0], p[1]);
            __syncwarp();
            if (lane == 0) {
                const unsigned int src_sa =
                    stage_sa + (unsigned)(i & 3) * 4096u + (unsigned)w * 256u;
                asm volatile("fence.proxy.async.shared::cta;" ::: "memory");
                asm volatile(
                    "cp.async.bulk.shared::cluster.shared::cta.mbarrier::complete_tx::bytes "
                    "[%0], [%1], 256, [%2];"
                    :: "r"(dst_ra[g][t & 1]), "r"(src_sa), "r"(mb_ra[g][t & 1]) : "memory");
            }
        }

        // ---- wait + reduce PREVIOUS iteration's group (flight hidden above) ----
        if (i >= 1 && tid < 128) {
            const int gp = (i - 1) & 1, tp = (i - 1) >> 1, sl = tp & 1;
            const unsigned int mb = mb_sa[gp * 2 + sl];
            const unsigned int parity = (unsigned)(tp >> 1) & 1u;
            unsigned int done;
            asm volatile(
                "{\n\t.reg .pred p;\n\t"
                "mbarrier.try_wait.parity.acquire.cluster.shared::cta.b64 p, [%1], %2;\n\t"
                "selp.b32 %0, 1, 0, p;\n\t}"
                : "=r"(done) : "r"(mb), "r"(parity) : "memory");
            if (!done) {
                asm volatile(
                    "{\n\t.reg .pred P1;\n\t"
                    "WL_%=:\n\t"
                    "mbarrier.try_wait.parity.acquire.cluster.shared::cta.b64 P1, [%0], %1, 0x989680;\n\t"
                    "@P1 bra.uni WD_%=;\n\t"
                    "bra.uni WL_%=;\n\t"
                    "WD_%=:\n\t}"
                    :: "r"(mb), "r"(parity) : "memory");
            }
            // Re-arm for next use (t+2) immediately
            if (tid == 0) {
                asm volatile("mbarrier.arrive.expect_tx.shared.b64 _, [%0], %1;"
                             :: "r"(mb), "r"(STEP_TX) : "memory");
            }
            float sum = xpv;
#pragma unroll
            for (int src = 0; src < CSZ; src++)
                sum += recv[gp][sl][src][tid];
            float val = tanhf(sum);
            h_own[gp][rb][rhl] = val;
            out[(size_t)(batch_base + gp * 2 + rb) * S_LEN * HID +
                (size_t)tp * HID + rank * KC + rhl] = val;
        }
        __syncthreads();   // publish h_own[gp] before its next compute (i+1)
    }

    // hidden = h_T for all 4 batches
    if (tid < 256) {
        const int b2 = tid & 3, g = b2 >> 1, b = b2 & 1, r2 = tid >> 2;
        out[(size_t)BATCH * S_LEN * HID +
            (size_t)(batch_base + g * 2 + b) * HID + rank * KC + r2] = h_own[g][b][r2];
    }

    asm volatile("barrier.cluster.arrive.aligned;" ::: "memory");
    asm volatile("barrier.cluster.wait.aligned;"   ::: "memory");
}

// ---------------------------------------------------------------------------
// Launch
// ---------------------------------------------------------------------------
extern "C" void kernel_launch(void* const* d_in, const int* in_sizes, int n_in,
                              void* d_out, int out_size)
{
    const void*  tok  = d_in[0];                 // (B,S) int32 or int64
    const float* emb  = (const float*)d_in[1];   // (V,E)
    const float* W_ih = (const float*)d_in[2];   // (H,E)
    const float* W_hh = (const float*)d_in[3];   // (H,H)
    const float* b_ih = (const float*)d_in[4];   // (H,)
    const float* b_hh = (const float*)d_in[5];   // (H,)
    float* out = (float*)d_out;                  // (B,S,H) outputs ++ (1,B,H) hidden

    dim3 grid_p1(HID / 128, (BATCH * S_LEN) / 128);   // (4, 256)
    xproj_kernel<<<grid_p1, 256>>>(tok, emb, W_ih, b_ih, b_hh);

    rnn_kernel<<<(BATCH / BG) * CSZ, 512>>>(W_hh, out);  // 128 CTAs = 16 clusters
}

// round 10
// speedup vs baseline: 1.3438x; 1.3438x over previous
#include <cuda_runtime.h>
#include <cstdint>
#include <cstddef>

// Problem dims
#define VOCAB 32000
#define EMB   512
#define HID   512
#define BATCH 64
#define S_LEN 512

// ---------------------------------------------------------------------------
// Scratch (no allocation allowed -> __device__ global)
// ---------------------------------------------------------------------------
__device__ float g_xproj[(size_t)BATCH * S_LEN * HID]; // 64 MB scratch

// ---------------------------------------------------------------------------
// Packed f32x2 helpers (Blackwell)
// ---------------------------------------------------------------------------
__device__ __forceinline__ unsigned long long packdup(float v) {
    unsigned long long r;
    asm("mov.b64 %0, {%1, %1};" : "=l"(r) : "f"(v));
    return r;
}
__device__ __forceinline__ void ffma2(unsigned long long& acc,
                                      unsigned long long a,
                                      unsigned long long b) {
    asm("fma.rn.f32x2 %0, %1, %2, %0;" : "+l"(acc) : "l"(a), "l"(b));
}
__device__ __forceinline__ float2 unpack2(unsigned long long v) {
    float2 f;
    asm("mov.b64 {%0, %1}, %2;" : "=f"(f.x), "=f"(f.y) : "l"(v));
    return f;
}

// ---------------------------------------------------------------------------
// Kernel 1: x_proj = gather(emb, tok) @ W_ih^T + (b_ih + b_hh)
// BM=BN=128, BK=16, 256 threads, 8x8/thread, f32x2 FFMA, conflict-free maps.
// (unchanged from R8)
// ---------------------------------------------------------------------------
__global__ void __launch_bounds__(256, 2)
xproj_kernel(const void* __restrict__ tok_raw,
             const float* __restrict__ emb,
             const float* __restrict__ W_ih,
             const float* __restrict__ b_ih,
             const float* __restrict__ b_hh)
{
    __shared__ float              As[16][128];      // A tile, [k][m]
    __shared__ unsigned long long Bsd[16][128];     // B tile, [k][n], dup {v,v}
    __shared__ int                toks[128];
    __shared__ int                s_tok64;

    const int tid = threadIdx.x;
    const int m0  = blockIdx.y * 128;
    const int n0  = blockIdx.x * 128;

    // int64 tokens (LE) => odd 32-bit words of the first 32 elements all zero.
    if (tid < 32) {
        int wv = ((const int*)tok_raw)[2 * tid + 1];
        unsigned nz = __ballot_sync(0xffffffffu, wv != 0);
        if (tid == 0) s_tok64 = (nz == 0u);
    }
    __syncthreads();

    if (tid < 128) {
        int m = m0 + tid;
        toks[tid] = s_tok64 ? (int)((const long long*)tok_raw)[m]
                            : ((const int*)tok_raw)[m];
    }
    __syncthreads();

    const int ldr_m   = tid & 127;
    const int ldr_seg = (tid >> 7) * 8;
    const float* arow_base = emb  + (size_t)toks[ldr_m] * EMB + ldr_seg;
    const float* brow_base = W_ih + (size_t)(n0 + ldr_m) * EMB + ldr_seg;

    const int ty = tid & 15;   // m sub-tile
    const int tx = tid >> 4;   // n sub-tile

    unsigned long long acc[32];
#pragma unroll
    for (int i = 0; i < 32; i++) acc[i] = 0ull;

    for (int kt = 0; kt < EMB / 16; kt++) {
        const int k0 = kt * 16;
        float4 av0 = *(const float4*)(arow_base + k0);
        float4 av1 = *(const float4*)(arow_base + k0 + 4);
        float4 bv0 = *(const float4*)(brow_base + k0);
        float4 bv1 = *(const float4*)(brow_base + k0 + 4);

        __syncthreads();
        As[ldr_seg + 0][ldr_m] = av0.x;
        As[ldr_seg + 1][ldr_m] = av0.y;
        As[ldr_seg + 2][ldr_m] = av0.z;
        As[ldr_seg + 3][ldr_m] = av0.w;
        As[ldr_seg + 4][ldr_m] = av1.x;
        As[ldr_seg + 5][ldr_m] = av1.y;
        As[ldr_seg + 6][ldr_m] = av1.z;
        As[ldr_seg + 7][ldr_m] = av1.w;
        Bsd[ldr_seg + 0][ldr_m] = packdup(bv0.x);
        Bsd[ldr_seg + 1][ldr_m] = packdup(bv0.y);
        Bsd[ldr_seg + 2][ldr_m] = packdup(bv0.z);
        Bsd[ldr_seg + 3][ldr_m] = packdup(bv0.w);
        Bsd[ldr_seg + 4][ldr_m] = packdup(bv1.x);
        Bsd[ldr_seg + 5][ldr_m] = packdup(bv1.y);
        Bsd[ldr_seg + 6][ldr_m] = packdup(bv1.z);
        Bsd[ldr_seg + 7][ldr_m] = packdup(bv1.w);
        __syncthreads();

#pragma unroll
        for (int kk = 0; kk < 16; kk++) {
            ulonglong2 a01 = *(const ulonglong2*)&As[kk][ty * 8];
            ulonglong2 a23 = *(const ulonglong2*)&As[kk][ty * 8 + 4];
            unsigned long long ap[4] = { a01.x, a01.y, a23.x, a23.y };
            ulonglong2 b01 = *(const ulonglong2*)&Bsd[kk][tx * 8];
            ulonglong2 b23 = *(const ulonglong2*)&Bsd[kk][tx * 8 + 2];
            ulonglong2 b45 = *(const ulonglong2*)&Bsd[kk][tx * 8 + 4];
            ulonglong2 b67 = *(const ulonglong2*)&Bsd[kk][tx * 8 + 6];
            unsigned long long bd[8] = { b01.x, b01.y, b23.x, b23.y,
                                         b45.x, b45.y, b67.x, b67.y };
#pragma unroll
            for (int i2 = 0; i2 < 4; i2++)
#pragma unroll
                for (int j = 0; j < 8; j++)
                    ffma2(acc[i2 * 8 + j], ap[i2], bd[j]);
        }
    }

    float bias[8];
    {
        float4 x0 = *(const float4*)(b_ih + n0 + tx * 8);
        float4 x1 = *(const float4*)(b_ih + n0 + tx * 8 + 4);
        float4 y0 = *(const float4*)(b_hh + n0 + tx * 8);
        float4 y1 = *(const float4*)(b_hh + n0 + tx * 8 + 4);
        bias[0] = x0.x + y0.x;  bias[1] = x0.y + y0.y;
        bias[2] = x0.z + y0.z;  bias[3] = x0.w + y0.w;
        bias[4] = x1.x + y1.x;  bias[5] = x1.y + y1.y;
        bias[6] = x1.z + y1.z;  bias[7] = x1.w + y1.w;
    }
#pragma unroll
    for (int i2 = 0; i2 < 4; i2++) {
        float r0[8], r1[8];
#pragma unroll
        for (int j = 0; j < 8; j++) {
            float2 f = unpack2(acc[i2 * 8 + j]);
            r0[j] = f.x + bias[j];
            r1[j] = f.y + bias[j];
        }
        size_t mg = (size_t)(m0 + ty * 8 + i2 * 2);
        float* o0 = g_xproj + mg * HID + n0 + tx * 8;
        float* o1 = o0 + HID;
        *(float4*)(o0)     = make_float4(r0[0], r0[1], r0[2], r0[3]);
        *(float4*)(o0 + 4) = make_float4(r0[4], r0[5], r0[6], r0[7]);
        *(float4*)(o1)     = make_float4(r1[0], r1[1], r1[2], r1[3]);
        *(float4*)(o1 + 4) = make_float4(r1[4], r1[5], r1[6], r1[7]);
    }
}

// ---------------------------------------------------------------------------
// Kernel 2: recurrence, 256 threads/CTA, TWO ROWS PER THREAD.
// 16 clusters x 8 CTAs; cluster owns 4 batches; CTA rank j holds
// W_hh[:, 64j:64j+64) in registers — thread t (warp w, lane l) holds rows
// 64w+l and 64w+l+32 (128 floats). One h LDS.128 now feeds 4 FFMA2
// (2 rows x 2), halving total LDS and issue pressure vs R8.
// Warp w's 1KB slab goes to owner CTA w (bijection). All 256 threads reduce
// (1 output value each). Double-buffered comm + h_own, 1 bar/step.
// ---------------------------------------------------------------------------
#define CSZ 8
#define BG  4
#define KC  64
#define STEP_TX 8192              /* 8 slabs x 1024 B per owner per step */

__global__ void __cluster_dims__(CSZ, 1, 1) __launch_bounds__(256, 1)
rnn_kernel(const float* __restrict__ W_hh, float* __restrict__ out)
{
    __shared__ float h_own[2][BG][KC];         // [buf][batch][row] 2 KB
    __shared__ float recv[2][CSZ][256];        // [buf][src][lane*8+j] 8 KB
    __shared__ float stage[2][CSZ][256];       // [buf][warp][lane*8+j] 8 KB
    __shared__ unsigned long long mbar[2];

    const int tid  = threadIdx.x;
    const int w    = tid >> 5;       // warp 0..7  == destination CTA
    const int lane = tid & 31;
    unsigned int rank;
    asm("mov.u32 %0, %%cluster_ctarank;" : "=r"(rank));
    const int batch_base = (blockIdx.x / CSZ) * BG;

    // Two register-resident W rows: r0 = 64w+lane, r1 = r0+32, cols [64*rank, +64)
    unsigned long long Wp0[KC / 2], Wp1[KC / 2];
    {
        const unsigned long long* wr0 =
            (const unsigned long long*)(W_hh + (size_t)(64 * w + lane) * HID + rank * KC);
        const unsigned long long* wr1 =
            (const unsigned long long*)(W_hh + (size_t)(64 * w + lane + 32) * HID + rank * KC);
#pragma unroll
        for (int i = 0; i < KC / 2; i++) { Wp0[i] = wr0[i]; Wp1[i] = wr1[i]; }
    }

    ((float*)h_own[0])[tid] = 0.0f;   // h0 = 0 (256 floats, buffer 0)

    // mbarrier init + pre-arm both slots
    const unsigned int mbar0 = (unsigned int)__cvta_generic_to_shared(&mbar[0]);
    const unsigned int mbar1 = (unsigned int)__cvta_generic_to_shared(&mbar[1]);
    if (tid == 0) {
        asm volatile("mbarrier.init.shared.b64 [%0], 1;" :: "r"(mbar0) : "memory");
        asm volatile("mbarrier.init.shared.b64 [%0], 1;" :: "r"(mbar1) : "memory");
        asm volatile("mbarrier.arrive.expect_tx.shared.b64 _, [%0], %1;"
                     :: "r"(mbar0), "r"(STEP_TX) : "memory");
        asm volatile("mbarrier.arrive.expect_tx.shared.b64 _, [%0], %1;"
                     :: "r"(mbar1), "r"(STEP_TX) : "memory");
    }

    // Reduce-role: thread t -> (rel = t>>2 in [0,64), b = t&3)
    const int rb  = tid & 3;
    const int rel = tid >> 2;
    const int ridx = (rel < 32) ? rel * 8 + rb : (rel - 32) * 8 + 4 + rb;
    const float* xp_base  = g_xproj + (size_t)(batch_base + rb) * S_LEN * HID + rank * KC + rel;
    float*       out_base = out     + (size_t)(batch_base + rb) * S_LEN * HID + rank * KC + rel;

    // Remote addresses: warp w sends its slab to CTA w's recv[buf][rank]
    const unsigned int stage_sa =
        (unsigned int)__cvta_generic_to_shared(&stage[0][0][0]);
    unsigned int dst_ra[2], mb_ra[2];
#pragma unroll
    for (int b = 0; b < 2; b++) {
        unsigned int la = (unsigned int)__cvta_generic_to_shared(&recv[b][rank][0]);
        unsigned int lm = b ? mbar1 : mbar0;
        asm("mapa.shared::cluster.u32 %0, %1, %2;" : "=r"(dst_ra[b]) : "r"(la), "r"((unsigned)w));
        asm("mapa.shared::cluster.u32 %0, %1, %2;" : "=r"(mb_ra[b])  : "r"(lm), "r"((unsigned)w));
    }

    __syncthreads();
    asm volatile("barrier.cluster.arrive.aligned;" ::: "memory");
    asm volatile("barrier.cluster.wait.aligned;"   ::: "memory");

    // xp prefetch pipeline
    float xpv_cur = __ldg(xp_base);

    for (int s = 0; s < S_LEN; s++) {
        const int cur = s & 1;
        const int nxt = cur ^ 1;

        float xpv_next = 0.0f;
        if (s + 1 < S_LEN) xpv_next = __ldg(xp_base + (size_t)(s + 1) * HID);

        // Partials: 2 rows x 4 batches, one h LDS feeds both rows
        float p0[BG], p1[BG];
#pragma unroll
        for (int b = 0; b < BG; b++) {
            unsigned long long a0 = 0ull, a1 = 0ull, c0 = 0ull, c1 = 0ull;
            const ulonglong2* hb = (const ulonglong2*)h_own[cur][b];
#pragma unroll
            for (int i = 0; i < KC / 4; i++) {
                ulonglong2 hv = hb[i];                 // broadcast LDS.128
                ffma2(a0, Wp0[2 * i],     hv.x);
                ffma2(a1, Wp0[2 * i + 1], hv.y);
                ffma2(c0, Wp1[2 * i],     hv.x);
                ffma2(c1, Wp1[2 * i + 1], hv.y);
            }
            unsigned long long sa, sc;
            asm("add.rn.f32x2 %0, %1, %2;" : "=l"(sa) : "l"(a0), "l"(a1));
            asm("add.rn.f32x2 %0, %1, %2;" : "=l"(sc) : "l"(c0), "l"(c1));
            float2 fa = unpack2(sa), fc = unpack2(sc);
            p0[b] = fa.x + fa.y;
            p1[b] = fc.x + fc.y;
        }

        // Stage 32B, warp-autonomous 1KB bulk send to owner CTA w
        *(float4*)&stage[cur][w][lane * 8]     = make_float4(p0[0], p0[1], p0[2], p0[3]);
        *(float4*)&stage[cur][w][lane * 8 + 4] = make_float4(p1[0], p1[1], p1[2], p1[3]);
        __syncwarp();
        if (lane == 0) {
            const unsigned int src_sa =
                stage_sa + (unsigned)cur * (CSZ * 1024u) + (unsigned)w * 1024u;
            asm volatile("fence.proxy.async.shared::cta;" ::: "memory");
            asm volatile(
                "cp.async.bulk.shared::cluster.shared::cta.mbarrier::complete_tx::bytes "
                "[%0], [%1], 1024, [%2];"
                :: "r"(dst_ra[cur]), "r"(src_sa), "r"(mb_ra[cur]) : "memory");
        }

        // Wait for all 8 slabs, re-arm, reduce (all 256 threads, 1 value each)
        {
            const unsigned int mb = cur ? mbar1 : mbar0;
            const unsigned int parity = (unsigned)(s >> 1) & 1u;
            unsigned int done;
            asm volatile(
                "{\n\t.reg .pred p;\n\t"
                "mbarrier.try_wait.parity.acquire.cluster.shared::cta.b64 p, [%1], %2;\n\t"
                "selp.b32 %0, 1, 0, p;\n\t}"
                : "=r"(done) : "r"(mb), "r"(parity) : "memory");
            if (!done) {
                asm volatile(
                    "{\n\t.reg .pred P1;\n\t"
                    "WL_%=:\n\t"
                    "mbarrier.try_wait.parity.acquire.cluster.shared::cta.b64 P1, [%0], %1, 0x989680;\n\t"
                    "@P1 bra.uni WD_%=;\n\t"
                    "bra.uni WL_%=;\n\t"
                    "WD_%=:\n\t}"
                    :: "r"(mb), "r"(parity) : "memory");
            }
            if (tid == 0) {
                asm volatile("mbarrier.arrive.expect_tx.shared.b64 _, [%0], %1;"
                             :: "r"(mb), "r"(STEP_TX) : "memory");
            }

            float sum = xpv_cur;
#pragma unroll
            for (int src = 0; src < CSZ; src++)
                sum += recv[cur][src][ridx];
            float val = tanhf(sum);
            h_own[nxt][rb][rel] = val;
            out_base[(size_t)s * HID] = val;
        }
        xpv_cur = xpv_next;
        __syncthreads();   // publish h_own[nxt]
    }

    // hidden = h_T (final state in buffer S_LEN&1 = 0)
    out[(size_t)BATCH * S_LEN * HID +
        (size_t)(batch_base + rb) * HID + rank * KC + rel] = h_own[S_LEN & 1][rb][rel];

    asm volatile("barrier.cluster.arrive.aligned;" ::: "memory");
    asm volatile("barrier.cluster.wait.aligned;"   ::: "memory");
}

// ---------------------------------------------------------------------------
// Launch
// ---------------------------------------------------------------------------
extern "C" void kernel_launch(void* const* d_in, const int* in_sizes, int n_in,
                              void* d_out, int out_size)
{
    const void*  tok  = d_in[0];                 // (B,S) int32 or int64
    const float* emb  = (const float*)d_in[1];   // (V,E)
    const float* W_ih = (const float*)d_in[2];   // (H,E)
    const float* W_hh = (const float*)d_in[3];   // (H,H)
    const float* b_ih = (const float*)d_in[4];   // (H,)
    const float* b_hh = (const float*)d_in[5];   // (H,)
    float* out = (float*)d_out;                  // (B,S,H) outputs ++ (1,B,H) hidden

    dim3 grid_p1(HID / 128, (BATCH * S_LEN) / 128);   // (4, 256)
    xproj_kernel<<<grid_p1, 256>>>(tok, emb, W_ih, b_ih, b_hh);

    rnn_kernel<<<(BATCH / BG) * CSZ, 256>>>(W_hh, out);  // 128 CTAs = 16 clusters
}